// round 1
// baseline (speedup 1.0000x reference)
#include <cuda_runtime.h>
#include <cuda_bf16.h>
#include <cstdint>

#define N_NODES_MAX 50000
#define DIM 128
#define BN_EPS 1e-5f

// ---------------- device scratch (no allocs allowed) ----------------
__device__ float g_h[N_NODES_MAX * DIM];      // x @ W
__device__ float g_agg[N_NODES_MAX * DIM];    // aggregated messages
__device__ float g_deg[N_NODES_MAX];
__device__ float g_dinv[N_NODES_MAX];
__device__ float g_stats[2 * DIM];            // [0:128) sum, [128:256) sumsq
__device__ float g_scale[DIM];
__device__ float g_shift[DIM];

// ---------------- init: deg = 1 (self loop), stats = 0 ----------------
__global__ void init_kernel(int n) {
    int i = blockIdx.x * blockDim.x + threadIdx.x;
    if (i < n) g_deg[i] = 1.0f;
    if (i < 2 * DIM) g_stats[i] = 0.0f;
}

// ---------------- degree over targets ----------------
__global__ void deg_kernel(const int* __restrict__ dst, int E) {
    int e = blockIdx.x * blockDim.x + threadIdx.x;
    if (e < E) atomicAdd(&g_deg[dst[e]], 1.0f);
}

__global__ void dinv_kernel(int n) {
    int i = blockIdx.x * blockDim.x + threadIdx.x;
    if (i < n) g_dinv[i] = rsqrtf(g_deg[i]);
}

// ---------------- GEMM h = x @ W, epilogue inits agg = h*dinv^2 + b ----
// Grid: (ceil(n/32), 2). Each block: 32 rows x 64 output dims.
// Thread layout (256 thr): c = t%16 (4 dims), rs = t/16 (2 rows each).
#define GROWS 32
#define GCOLS 64
__global__ __launch_bounds__(256) void gemm_kernel(
    const float* __restrict__ x, const float* __restrict__ W,
    const float* __restrict__ b, int n)
{
    __shared__ float Ws[DIM][GCOLS];          // 32 KB
    __shared__ float xs[GROWS][DIM + 4];      // 16.5 KB, stride 132 floats (528B, 16B-aligned)

    const int t = threadIdx.x;
    const int c0 = blockIdx.y * GCOLS;
    const int row0 = blockIdx.x * GROWS;

    // stage W[:, c0:c0+64]
    for (int i = t * 4; i < DIM * GCOLS; i += 256 * 4) {
        int k = i / GCOLS, c = i % GCOLS;
        *(float4*)&Ws[k][c] = *(const float4*)(W + (size_t)k * DIM + c0 + c);
    }
    // stage 32 rows of x
    for (int i = t; i < GROWS * (DIM / 4); i += 256) {
        int r = i / 32, cc = (i % 32) * 4;
        int row = row0 + r;
        float4 v = make_float4(0.f, 0.f, 0.f, 0.f);
        if (row < n) v = *(const float4*)(x + (size_t)row * DIM + cc);
        *(float4*)&xs[r][cc] = v;
    }
    __syncthreads();

    const int c = t & 15;       // dim group (4 dims)
    const int r0 = (t >> 4) * 2;

    float4 a0 = make_float4(0.f, 0.f, 0.f, 0.f);
    float4 a1 = make_float4(0.f, 0.f, 0.f, 0.f);
#pragma unroll 8
    for (int k = 0; k < DIM; k++) {
        float4 w = *(float4*)&Ws[k][c * 4];
        float v0 = xs[r0][k];
        float v1 = xs[r0 + 1][k];
        a0.x += v0 * w.x; a0.y += v0 * w.y; a0.z += v0 * w.z; a0.w += v0 * w.w;
        a1.x += v1 * w.x; a1.y += v1 * w.y; a1.z += v1 * w.z; a1.w += v1 * w.w;
    }

    float4 bv = *(const float4*)(b + c0 + c * 4);
#pragma unroll
    for (int rr = 0; rr < 2; rr++) {
        int row = row0 + r0 + rr;
        if (row >= n) break;
        float4 a = rr ? a1 : a0;
        size_t off = (size_t)row * DIM + c0 + c * 4;
        *(float4*)(g_h + off) = a;
        float di = g_dinv[row];
        float sn = di * di;   // self-loop norm
        float4 ag;
        ag.x = a.x * sn + bv.x; ag.y = a.y * sn + bv.y;
        ag.z = a.z * sn + bv.z; ag.w = a.w * sn + bv.w;
        *(float4*)(g_agg + off) = ag;
    }
}

// ---------------- edge scatter: one warp per edge, 4 edges/warp -------
#define EPW 4
__global__ __launch_bounds__(256) void scatter_kernel(
    const int* __restrict__ src, const int* __restrict__ dst, int E)
{
    const int lane = threadIdx.x & 31;
    const int warp = (blockIdx.x * blockDim.x + threadIdx.x) >> 5;
    int e0 = warp * EPW;
#pragma unroll
    for (int i = 0; i < EPW; i++) {
        int e = e0 + i;
        if (e >= E) return;
        int s = __ldg(src + e);
        int d = __ldg(dst + e);
        float nm = __ldg(g_dinv + s) * __ldg(g_dinv + d);
        float4 v = __ldg((const float4*)(g_h + (size_t)s * DIM) + lane);
        float* ap = g_agg + (size_t)d * DIM + lane * 4;
        asm volatile("red.global.add.v4.f32 [%0], {%1,%2,%3,%4};"
                     :: "l"(ap), "f"(v.x * nm), "f"(v.y * nm),
                        "f"(v.z * nm), "f"(v.w * nm)
                     : "memory");
    }
}

// ---------------- BN stats: per-dim sum & sumsq -----------------------
__global__ __launch_bounds__(128) void stats_kernel(int n) {
    int d = threadIdx.x;
    float s = 0.f, s2 = 0.f;
    for (int r = blockIdx.x; r < n; r += gridDim.x) {
        float v = g_agg[(size_t)r * DIM + d];
        s += v; s2 += v * v;
    }
    atomicAdd(&g_stats[d], s);
    atomicAdd(&g_stats[DIM + d], s2);
}

__global__ void finalize_kernel(const float* __restrict__ gamma,
                                const float* __restrict__ beta, float inv_n) {
    int d = threadIdx.x;
    float mean = g_stats[d] * inv_n;
    float var  = g_stats[DIM + d] * inv_n - mean * mean;
    float sc = gamma[d] * rsqrtf(var + BN_EPS);
    g_scale[d] = sc;
    g_shift[d] = beta[d] - mean * sc;
}

// ---------------- epilogue: relu(BN(agg)) + x -------------------------
__global__ __launch_bounds__(256) void out_kernel(
    const float* __restrict__ x, float* __restrict__ out, int total4)
{
    int i = blockIdx.x * blockDim.x + threadIdx.x;
    if (i >= total4) return;
    int d4 = i & 31;
    float4 a  = ((const float4*)g_agg)[i];
    float4 sc = ((const float4*)g_scale)[d4];
    float4 sh = ((const float4*)g_shift)[d4];
    float4 xv = ((const float4*)x)[i];
    float4 y;
    y.x = fmaxf(a.x * sc.x + sh.x, 0.f) + xv.x;
    y.y = fmaxf(a.y * sc.y + sh.y, 0.f) + xv.y;
    y.z = fmaxf(a.z * sc.z + sh.z, 0.f) + xv.z;
    y.w = fmaxf(a.w * sc.w + sh.w, 0.f) + xv.w;
    ((float4*)out)[i] = y;
}

// ---------------- launch ----------------------------------------------
extern "C" void kernel_launch(void* const* d_in, const int* in_sizes, int n_in,
                              void* d_out, int out_size)
{
    const float* x     = (const float*)d_in[0];
    const float* W     = (const float*)d_in[1];
    const float* b     = (const float*)d_in[2];
    const float* gamma = (const float*)d_in[3];
    const float* beta  = (const float*)d_in[4];
    const int*   ei    = (const int*)d_in[5];

    const int n = in_sizes[0] / DIM;
    const int E = in_sizes[5] / 2;
    const int* src = ei;
    const int* dst = ei + E;

    // 1. init (deg=1, stats=0)
    {
        int tot = n > 2 * DIM ? n : 2 * DIM;
        init_kernel<<<(tot + 255) / 256, 256>>>(n);
    }
    // 2. degrees over targets
    deg_kernel<<<(E + 255) / 256, 256>>>(dst, E);
    // 3. dinv
    dinv_kernel<<<(n + 255) / 256, 256>>>(n);
    // 4. GEMM + self-loop/bias agg init
    {
        dim3 grid((n + GROWS - 1) / GROWS, DIM / GCOLS);
        gemm_kernel<<<grid, 256>>>(x, W, b, n);
    }
    // 5. edge scatter
    {
        int warps = (E + EPW - 1) / EPW;
        int blocks = (warps + 7) / 8;
        scatter_kernel<<<blocks, 256>>>(src, dst, E);
    }
    // 6. BN stats
    stats_kernel<<<512, 128>>>(n);
    // 7. finalize scale/shift
    finalize_kernel<<<1, DIM>>>(gamma, beta, 1.0f / (float)n);
    // 8. output
    {
        int total4 = n * DIM / 4;
        out_kernel<<<(total4 + 255) / 256, 256>>>(x, (float*)d_out, total4);
    }
}

// round 2
// speedup vs baseline: 1.4508x; 1.4508x over previous
#include <cuda_runtime.h>
#include <cuda_bf16.h>
#include <cstdint>

#define N_NODES_MAX 50048
#define E_MAX 1600000
#define DIM 128
#define BN_EPS 1e-5f

// ---------------- device scratch ----------------
__device__ float g_h[N_NODES_MAX * DIM];      // x @ W
__device__ float g_agg[N_NODES_MAX * DIM];    // aggregated messages
__device__ float g_dinv[N_NODES_MAX];
__device__ int   g_cnt[N_NODES_MAX];          // edge-only in-degree
__device__ int   g_row[N_NODES_MAX];          // CSR row starts (exclusive scan)
__device__ int   g_fill[N_NODES_MAX];         // fill cursors
__device__ int   g_part[64];                  // scan partials
__device__ int   g_esrc[E_MAX];               // CSR column (src) indices
__device__ float g_stats[2 * DIM];
__device__ float g_scale[DIM];
__device__ float g_shift[DIM];

// ---------------- init: zero counts/cursors/stats ----------------
__global__ void init_kernel(int n) {
    int i = blockIdx.x * blockDim.x + threadIdx.x;
    if (i < n) { g_cnt[i] = 0; g_fill[i] = 0; }
    if (i < 2 * DIM) g_stats[i] = 0.0f;
}

// ---------------- in-degree over targets (edges only) ----------------
__global__ void deg_kernel(const int* __restrict__ dst, int E) {
    int e = blockIdx.x * blockDim.x + threadIdx.x;
    if (e < E) atomicAdd(&g_cnt[dst[e]], 1);
}

__global__ void dinv_kernel(int n) {
    int i = blockIdx.x * blockDim.x + threadIdx.x;
    if (i < n) g_dinv[i] = rsqrtf((float)(g_cnt[i] + 1));   // +1 self loop
}

// ---------------- exclusive scan of g_cnt -> g_row (3 kernels) --------
__global__ __launch_bounds__(1024) void scan1_kernel(int n) {
    __shared__ int wsum[32];
    int i = blockIdx.x * 1024 + threadIdx.x;
    int lane = threadIdx.x & 31, wid = threadIdx.x >> 5;
    int v = (i < n) ? g_cnt[i] : 0;
    int s = v;
#pragma unroll
    for (int o = 1; o < 32; o <<= 1) {
        int t = __shfl_up_sync(0xffffffffu, s, o);
        if (lane >= o) s += t;
    }
    if (lane == 31) wsum[wid] = s;
    __syncthreads();
    if (wid == 0) {
        int ws = wsum[lane];
#pragma unroll
        for (int o = 1; o < 32; o <<= 1) {
            int t = __shfl_up_sync(0xffffffffu, ws, o);
            if (lane >= o) ws += t;
        }
        wsum[lane] = ws;
    }
    __syncthreads();
    int base = (wid > 0) ? wsum[wid - 1] : 0;
    if (i < n) g_row[i] = s - v + base;
    if (threadIdx.x == 1023) g_part[blockIdx.x] = s + base;
}

__global__ void scan2_kernel(int nb) {
    if (threadIdx.x == 0) {
        int acc = 0;
        for (int b = 0; b < nb; b++) { int t = g_part[b]; g_part[b] = acc; acc += t; }
    }
}

__global__ __launch_bounds__(1024) void scan3_kernel(int n) {
    int i = blockIdx.x * 1024 + threadIdx.x;
    if (i < n) g_row[i] += g_part[blockIdx.x];
}

// ---------------- fill CSR ----------------
__global__ void fill_kernel(const int* __restrict__ src,
                            const int* __restrict__ dst, int E) {
    int e = blockIdx.x * blockDim.x + threadIdx.x;
    if (e < E) {
        int d = dst[e];
        int pos = g_row[d] + atomicAdd(&g_fill[d], 1);
        g_esrc[pos] = src[e];
    }
}

// ---------------- GEMM h = x @ W -------------------------------------
// Block: 64 rows x 128 cols, K in 4 chunks of 32.
// Thread (256): cid = t&31 -> 4 cols, rid = t>>5 -> 8 rows. 32 outputs/thr.
#define TR 64
#define KC 32
__global__ __launch_bounds__(256) void gemm_kernel(
    const float* __restrict__ x, const float* __restrict__ W, int n)
{
    __shared__ float Ws[KC][DIM];       // 16 KB
    __shared__ float xsT[KC][TR + 8];   // k-major, pad 8 (stride 288B, 16B-aligned)

    const int t = threadIdx.x;
    const int row0 = blockIdx.x * TR;
    const int cid = t & 31;
    const int rid = t >> 5;

    float4 acc[8];
#pragma unroll
    for (int i = 0; i < 8; i++) acc[i] = make_float4(0.f, 0.f, 0.f, 0.f);

    for (int k0 = 0; k0 < DIM; k0 += KC) {
        // stage W chunk [KC x DIM]
        for (int i = t; i < KC * (DIM / 4); i += 256) {
            int k = i / (DIM / 4), c = (i % (DIM / 4)) * 4;
            *(float4*)&Ws[k][c] = *(const float4*)(W + (size_t)(k0 + k) * DIM + c);
        }
        // stage x chunk transposed: xsT[k][r]
        for (int i = t; i < TR * (KC / 4); i += 256) {
            int r = i / (KC / 4), kk = (i % (KC / 4)) * 4;
            int row = row0 + r;
            float4 v = make_float4(0.f, 0.f, 0.f, 0.f);
            if (row < n) v = *(const float4*)(x + (size_t)row * DIM + k0 + kk);
            xsT[kk + 0][r] = v.x; xsT[kk + 1][r] = v.y;
            xsT[kk + 2][r] = v.z; xsT[kk + 3][r] = v.w;
        }
        __syncthreads();
#pragma unroll
        for (int k = 0; k < KC; k++) {
            float4 w  = *(float4*)&Ws[k][cid * 4];
            float4 xa = *(float4*)&xsT[k][rid * 8];
            float4 xb = *(float4*)&xsT[k][rid * 8 + 4];
            acc[0].x += xa.x * w.x; acc[0].y += xa.x * w.y; acc[0].z += xa.x * w.z; acc[0].w += xa.x * w.w;
            acc[1].x += xa.y * w.x; acc[1].y += xa.y * w.y; acc[1].z += xa.y * w.z; acc[1].w += xa.y * w.w;
            acc[2].x += xa.z * w.x; acc[2].y += xa.z * w.y; acc[2].z += xa.z * w.z; acc[2].w += xa.z * w.w;
            acc[3].x += xa.w * w.x; acc[3].y += xa.w * w.y; acc[3].z += xa.w * w.z; acc[3].w += xa.w * w.w;
            acc[4].x += xb.x * w.x; acc[4].y += xb.x * w.y; acc[4].z += xb.x * w.z; acc[4].w += xb.x * w.w;
            acc[5].x += xb.y * w.x; acc[5].y += xb.y * w.y; acc[5].z += xb.y * w.z; acc[5].w += xb.y * w.w;
            acc[6].x += xb.z * w.x; acc[6].y += xb.z * w.y; acc[6].z += xb.z * w.z; acc[6].w += xb.z * w.w;
            acc[7].x += xb.w * w.x; acc[7].y += xb.w * w.y; acc[7].z += xb.w * w.z; acc[7].w += xb.w * w.w;
        }
        __syncthreads();
    }
#pragma unroll
    for (int rr = 0; rr < 8; rr++) {
        int row = row0 + rid * 8 + rr;
        if (row < n)
            *(float4*)(g_h + (size_t)row * DIM + cid * 4) = acc[rr];
    }
}

// ---------------- per-node accumulate (one warp per node) ------------
__global__ __launch_bounds__(256) void acc_kernel(const float* __restrict__ b, int n)
{
    int w = (blockIdx.x * blockDim.x + threadIdx.x) >> 5;
    if (w >= n) return;
    const int lane = threadIdx.x & 31;

    float di = g_dinv[w];
    float sn = di * di;
    float4 bv = __ldg((const float4*)b + lane);
    float4 hv = *((const float4*)(g_h + (size_t)w * DIM) + lane);
    float4 acc;
    acc.x = hv.x * sn + bv.x; acc.y = hv.y * sn + bv.y;
    acc.z = hv.z * sn + bv.z; acc.w = hv.w * sn + bv.w;

    int beg = g_row[w];
    int cnt = g_cnt[w];
#pragma unroll 4
    for (int j = 0; j < cnt; j++) {
        int s = __ldg(g_esrc + beg + j);
        float nm = di * __ldg(g_dinv + s);
        float4 v = __ldg((const float4*)(g_h + (size_t)s * DIM) + lane);
        acc.x += v.x * nm; acc.y += v.y * nm;
        acc.z += v.z * nm; acc.w += v.w * nm;
    }
    *((float4*)(g_agg + (size_t)w * DIM) + lane) = acc;
}

// ---------------- BN stats ----------------
__global__ __launch_bounds__(128) void stats_kernel(int n) {
    int d = threadIdx.x;
    float s = 0.f, s2 = 0.f;
    for (int r = blockIdx.x; r < n; r += gridDim.x) {
        float v = g_agg[(size_t)r * DIM + d];
        s += v; s2 += v * v;
    }
    atomicAdd(&g_stats[d], s);
    atomicAdd(&g_stats[DIM + d], s2);
}

__global__ void finalize_kernel(const float* __restrict__ gamma,
                                const float* __restrict__ beta, float inv_n) {
    int d = threadIdx.x;
    float mean = g_stats[d] * inv_n;
    float var  = g_stats[DIM + d] * inv_n - mean * mean;
    float sc = gamma[d] * rsqrtf(var + BN_EPS);
    g_scale[d] = sc;
    g_shift[d] = beta[d] - mean * sc;
}

// ---------------- epilogue: relu(BN(agg)) + x -------------------------
__global__ __launch_bounds__(256) void out_kernel(
    const float* __restrict__ x, float* __restrict__ out, int total4)
{
    int i = blockIdx.x * blockDim.x + threadIdx.x;
    if (i >= total4) return;
    int d4 = i & 31;
    float4 a  = ((const float4*)g_agg)[i];
    float4 sc = ((const float4*)g_scale)[d4];
    float4 sh = ((const float4*)g_shift)[d4];
    float4 xv = ((const float4*)x)[i];
    float4 y;
    y.x = fmaxf(a.x * sc.x + sh.x, 0.f) + xv.x;
    y.y = fmaxf(a.y * sc.y + sh.y, 0.f) + xv.y;
    y.z = fmaxf(a.z * sc.z + sh.z, 0.f) + xv.z;
    y.w = fmaxf(a.w * sc.w + sh.w, 0.f) + xv.w;
    ((float4*)out)[i] = y;
}

// ---------------- launch ----------------------------------------------
extern "C" void kernel_launch(void* const* d_in, const int* in_sizes, int n_in,
                              void* d_out, int out_size)
{
    const float* x     = (const float*)d_in[0];
    const float* W     = (const float*)d_in[1];
    const float* b     = (const float*)d_in[2];
    const float* gamma = (const float*)d_in[3];
    const float* beta  = (const float*)d_in[4];
    const int*   ei    = (const int*)d_in[5];

    const int n = in_sizes[0] / DIM;
    const int E = in_sizes[5] / 2;
    const int* src = ei;
    const int* dst = ei + E;

    // 1. init
    init_kernel<<<(n + 255) / 256, 256>>>(n);
    // 2. in-degree
    deg_kernel<<<(E + 255) / 256, 256>>>(dst, E);
    // 3. dinv
    dinv_kernel<<<(n + 255) / 256, 256>>>(n);
    // 4. exclusive scan -> CSR row starts
    int nb = (n + 1023) / 1024;
    scan1_kernel<<<nb, 1024>>>(n);
    scan2_kernel<<<1, 32>>>(nb);
    scan3_kernel<<<nb, 1024>>>(n);
    // 5. fill CSR
    fill_kernel<<<(E + 255) / 256, 256>>>(src, dst, E);
    // 6. GEMM
    gemm_kernel<<<(n + TR - 1) / TR, 256>>>(x, W, n);
    // 7. per-node accumulate (warp per node)
    {
        int warps = n;
        int blocks = (warps + 7) / 8;
        acc_kernel<<<blocks, 256>>>(b, n);
    }
    // 8. BN stats
    stats_kernel<<<512, 128>>>(n);
    // 9. finalize
    finalize_kernel<<<1, DIM>>>(gamma, beta, 1.0f / (float)n);
    // 10. output
    {
        int total4 = n * DIM / 4;
        out_kernel<<<(total4 + 255) / 256, 256>>>(x, (float*)d_out, total4);
    }
}

// round 4
// speedup vs baseline: 1.4845x; 1.0232x over previous
#include <cuda_runtime.h>
#include <cuda_bf16.h>
#include <cstdint>

#define N_NODES_MAX 50048
#define E_MAX 1600000
#define DIM 128
#define BN_EPS 1e-5f

// ---------------- device scratch ----------------
__device__ float g_h[N_NODES_MAX * DIM];
__device__ float g_agg[N_NODES_MAX * DIM];
__device__ float g_dinv[N_NODES_MAX];
__device__ int   g_cnt[N_NODES_MAX];
__device__ int   g_row[N_NODES_MAX];
__device__ int   g_fill[N_NODES_MAX];
__device__ int   g_part[64];
__device__ int   g_esrc[E_MAX];
__device__ float g_stats[2 * DIM];
__device__ float g_scale[DIM];
__device__ float g_shift[DIM];

// ---------------- init ----------------
__global__ void init_kernel(int n) {
    int i = blockIdx.x * blockDim.x + threadIdx.x;
    if (i < n) { g_cnt[i] = 0; g_fill[i] = 0; }
    if (i < 2 * DIM) g_stats[i] = 0.0f;
}

__global__ void deg_kernel(const int* __restrict__ dst, int E) {
    int e = blockIdx.x * blockDim.x + threadIdx.x;
    if (e < E) atomicAdd(&g_cnt[dst[e]], 1);
}

__global__ void dinv_kernel(int n) {
    int i = blockIdx.x * blockDim.x + threadIdx.x;
    if (i < n) g_dinv[i] = rsqrtf((float)(g_cnt[i] + 1));
}

// ---------------- exclusive scan ----------------
__global__ __launch_bounds__(1024) void scan1_kernel(int n) {
    __shared__ int wsum[32];
    int i = blockIdx.x * 1024 + threadIdx.x;
    int lane = threadIdx.x & 31, wid = threadIdx.x >> 5;
    int v = (i < n) ? g_cnt[i] : 0;
    int s = v;
#pragma unroll
    for (int o = 1; o < 32; o <<= 1) {
        int t = __shfl_up_sync(0xffffffffu, s, o);
        if (lane >= o) s += t;
    }
    if (lane == 31) wsum[wid] = s;
    __syncthreads();
    if (wid == 0) {
        int ws = wsum[lane];
#pragma unroll
        for (int o = 1; o < 32; o <<= 1) {
            int t = __shfl_up_sync(0xffffffffu, ws, o);
            if (lane >= o) ws += t;
        }
        wsum[lane] = ws;
    }
    __syncthreads();
    int base = (wid > 0) ? wsum[wid - 1] : 0;
    if (i < n) g_row[i] = s - v + base;
    if (threadIdx.x == 1023) g_part[blockIdx.x] = s + base;
}

__global__ void scan2_kernel(int nb) {
    if (threadIdx.x == 0) {
        int acc = 0;
        for (int b = 0; b < nb; b++) { int t = g_part[b]; g_part[b] = acc; acc += t; }
    }
}

__global__ __launch_bounds__(1024) void scan3_kernel(int n) {
    int i = blockIdx.x * 1024 + threadIdx.x;
    if (i < n) g_row[i] += g_part[blockIdx.x];
}

__global__ void fill_kernel(const int* __restrict__ src,
                            const int* __restrict__ dst, int E) {
    int e = blockIdx.x * blockDim.x + threadIdx.x;
    if (e < E) {
        int d = dst[e];
        int pos = g_row[d] + atomicAdd(&g_fill[d], 1);
        g_esrc[pos] = src[e];
    }
}

// ---------------- 3xTF32 tensor-core GEMM: h = x @ W ------------------
// Block: 128 rows x 128 cols. 8 warps: rowg = wid&3 (32 rows), colg = wid>>2 (64 cols).
// Warp tile: 32x64, per-lane accum 64 f32. K staged in 4 chunks of 32.
__device__ __forceinline__ void split_tf32(float v, uint32_t& hi, uint32_t& lo) {
    uint32_t h;
    asm("cvt.rna.tf32.f32 %0, %1;" : "=r"(h) : "f"(v));
    float lf = v - __uint_as_float(h);
    asm("cvt.rna.tf32.f32 %0, %1;" : "=r"(lo) : "f"(lf));
    hi = h;
}

__device__ __forceinline__ void mma_tf32(float* c, uint32_t a0, uint32_t a1,
                                         uint32_t a2, uint32_t a3,
                                         uint32_t b0, uint32_t b1) {
    asm volatile(
        "mma.sync.aligned.m16n8k8.row.col.f32.tf32.tf32.f32 "
        "{%0,%1,%2,%3}, {%4,%5,%6,%7}, {%8,%9}, {%0,%1,%2,%3};"
        : "+f"(c[0]), "+f"(c[1]), "+f"(c[2]), "+f"(c[3])
        : "r"(a0), "r"(a1), "r"(a2), "r"(a3), "r"(b0), "r"(b1));
}

#define KC 32
__global__ __launch_bounds__(256, 2) void gemm_tc_kernel(
    const float* __restrict__ x, const float* __restrict__ W, int n)
{
    __shared__ float xs[128][36];   // [row][k] chunk, pad 36 (144B rows, 16B aligned)
    __shared__ float ws[KC][132];   // [k][n], pad 132 (528B rows, 16B aligned)

    const int t = threadIdx.x;
    const int wid = t >> 5, lane = t & 31;
    const int rowg = wid & 3, colg = wid >> 2;
    const int g = lane >> 2, t4 = lane & 3;
    const int row0 = blockIdx.x * 128;

    float acc[2][8][4];
#pragma unroll
    for (int mi = 0; mi < 2; mi++)
#pragma unroll
        for (int nt = 0; nt < 8; nt++)
#pragma unroll
            for (int c = 0; c < 4; c++) acc[mi][nt][c] = 0.f;

    for (int kc = 0; kc < DIM; kc += KC) {
        // stage x chunk: 128 rows x 32 k
        for (int idx = t; idx < 1024; idx += 256) {
            int r = idx >> 3, k4 = (idx & 7) << 2;
            int row = row0 + r;
            float4 v = make_float4(0.f, 0.f, 0.f, 0.f);
            if (row < n) v = *(const float4*)(x + (size_t)row * DIM + kc + k4);
            *(float4*)&xs[r][k4] = v;
        }
        // stage W chunk: 32 k x 128 n
        for (int idx = t; idx < 1024; idx += 256) {
            int k = idx >> 5, n4 = (idx & 31) << 2;
            *(float4*)&ws[k][n4] = *(const float4*)(W + (size_t)(kc + k) * DIM + n4);
        }
        __syncthreads();

#pragma unroll
        for (int ks = 0; ks < KC; ks += 8) {
            // A fragments: 2 m16 tiles, split hi/lo
            uint32_t ahi[2][4], alo[2][4];
#pragma unroll
            for (int mi = 0; mi < 2; mi++) {
                int rb = rowg * 32 + mi * 16;
                split_tf32(xs[rb + g][ks + t4],          ahi[mi][0], alo[mi][0]);
                split_tf32(xs[rb + g + 8][ks + t4],      ahi[mi][1], alo[mi][1]);
                split_tf32(xs[rb + g][ks + t4 + 4],      ahi[mi][2], alo[mi][2]);
                split_tf32(xs[rb + g + 8][ks + t4 + 4],  ahi[mi][3], alo[mi][3]);
            }
#pragma unroll
            for (int nt = 0; nt < 8; nt++) {
                int cb = colg * 64 + nt * 8;
                uint32_t bhi0, blo0, bhi1, blo1;
                split_tf32(ws[ks + t4][cb + g],     bhi0, blo0);
                split_tf32(ws[ks + t4 + 4][cb + g], bhi1, blo1);
#pragma unroll
                for (int mi = 0; mi < 2; mi++) {
                    mma_tf32(acc[mi][nt], ahi[mi][0], ahi[mi][1], ahi[mi][2], ahi[mi][3], bhi0, bhi1);
                    mma_tf32(acc[mi][nt], ahi[mi][0], ahi[mi][1], ahi[mi][2], ahi[mi][3], blo0, blo1);
                    mma_tf32(acc[mi][nt], alo[mi][0], alo[mi][1], alo[mi][2], alo[mi][3], bhi0, bhi1);
                }
            }
        }
        __syncthreads();
    }

    // epilogue: D fragment (16x8): c0 at (g, 2*t4), c1 +1 col, c2/c3 at row+8
#pragma unroll
    for (int mi = 0; mi < 2; mi++) {
        int rb = row0 + rowg * 32 + mi * 16;
#pragma unroll
        for (int nt = 0; nt < 8; nt++) {
            int col = colg * 64 + nt * 8 + 2 * t4;
            int r0 = rb + g, r1 = rb + g + 8;
            if (r0 < n)
                *(float2*)(g_h + (size_t)r0 * DIM + col) = make_float2(acc[mi][nt][0], acc[mi][nt][1]);
            if (r1 < n)
                *(float2*)(g_h + (size_t)r1 * DIM + col) = make_float2(acc[mi][nt][2], acc[mi][nt][3]);
        }
    }
}

// ---------------- per-node accumulate + fused BN stats ----------------
__global__ __launch_bounds__(256) void acc_kernel(const float* __restrict__ b, int n)
{
    __shared__ float ssum[8][128];
    __shared__ float ssq[8][128];
    const int w = (blockIdx.x * blockDim.x + threadIdx.x) >> 5;
    const int wid = threadIdx.x >> 5;
    const int lane = threadIdx.x & 31;

    float4 acc = make_float4(0.f, 0.f, 0.f, 0.f);
    if (w < n) {
        float di = g_dinv[w];
        float sn = di * di;
        float4 bv = __ldg((const float4*)b + lane);
        float4 hv = *((const float4*)(g_h + (size_t)w * DIM) + lane);
        acc.x = hv.x * sn + bv.x; acc.y = hv.y * sn + bv.y;
        acc.z = hv.z * sn + bv.z; acc.w = hv.w * sn + bv.w;

        int beg = g_row[w];
        int cnt = g_cnt[w];
#pragma unroll 4
        for (int j = 0; j < cnt; j++) {
            int s = __ldg(g_esrc + beg + j);
            float nm = di * __ldg(g_dinv + s);
            float4 v = __ldg((const float4*)(g_h + (size_t)s * DIM) + lane);
            acc.x += v.x * nm; acc.y += v.y * nm;
            acc.z += v.z * nm; acc.w += v.w * nm;
        }
        *((float4*)(g_agg + (size_t)w * DIM) + lane) = acc;
    }
    *(float4*)&ssum[wid][lane * 4] = acc;
    float4 sq = make_float4(acc.x * acc.x, acc.y * acc.y, acc.z * acc.z, acc.w * acc.w);
    *(float4*)&ssq[wid][lane * 4] = sq;
    __syncthreads();

    int t = threadIdx.x;
    if (t < 128) {
        float s = 0.f;
#pragma unroll
        for (int k = 0; k < 8; k++) s += ssum[k][t];
        atomicAdd(&g_stats[t], s);
    } else {
        int d = t - 128;
        float s = 0.f;
#pragma unroll
        for (int k = 0; k < 8; k++) s += ssq[k][d];
        atomicAdd(&g_stats[DIM + d], s);
    }
}

__global__ void finalize_kernel(const float* __restrict__ gamma,
                                const float* __restrict__ beta, float inv_n) {
    int d = threadIdx.x;
    float mean = g_stats[d] * inv_n;
    float var  = g_stats[DIM + d] * inv_n - mean * mean;
    float sc = gamma[d] * rsqrtf(var + BN_EPS);
    g_scale[d] = sc;
    g_shift[d] = beta[d] - mean * sc;
}

__global__ __launch_bounds__(256) void out_kernel(
    const float* __restrict__ x, float* __restrict__ out, int total4)
{
    int i = blockIdx.x * blockDim.x + threadIdx.x;
    if (i >= total4) return;
    int d4 = i & 31;
    float4 a  = ((const float4*)g_agg)[i];
    float4 sc = ((const float4*)g_scale)[d4];
    float4 sh = ((const float4*)g_shift)[d4];
    float4 xv = ((const float4*)x)[i];
    float4 y;
    y.x = fmaxf(a.x * sc.x + sh.x, 0.f) + xv.x;
    y.y = fmaxf(a.y * sc.y + sh.y, 0.f) + xv.y;
    y.z = fmaxf(a.z * sc.z + sh.z, 0.f) + xv.z;
    y.w = fmaxf(a.w * sc.w + sh.w, 0.f) + xv.w;
    ((float4*)out)[i] = y;
}

// ---------------- launch ----------------------------------------------
extern "C" void kernel_launch(void* const* d_in, const int* in_sizes, int n_in,
                              void* d_out, int out_size)
{
    const float* x     = (const float*)d_in[0];
    const float* W     = (const float*)d_in[1];
    const float* b     = (const float*)d_in[2];
    const float* gamma = (const float*)d_in[3];
    const float* beta  = (const float*)d_in[4];
    const int*   ei    = (const int*)d_in[5];

    const int n = in_sizes[0] / DIM;
    const int E = in_sizes[5] / 2;
    const int* src = ei;
    const int* dst = ei + E;

    init_kernel<<<(n + 255) / 256, 256>>>(n);
    deg_kernel<<<(E + 255) / 256, 256>>>(dst, E);
    dinv_kernel<<<(n + 255) / 256, 256>>>(n);

    int nb = (n + 1023) / 1024;
    scan1_kernel<<<nb, 1024>>>(n);
    scan2_kernel<<<1, 32>>>(nb);
    scan3_kernel<<<nb, 1024>>>(n);
    fill_kernel<<<(E + 255) / 256, 256>>>(src, dst, E);

    gemm_tc_kernel<<<(n + 127) / 128, 256>>>(x, W, n);

    {
        int blocks = (n + 7) / 8;
        acc_kernel<<<blocks, 256>>>(b, n);
    }
    finalize_kernel<<<1, DIM>>>(gamma, beta, 1.0f / (float)n);
    {
        int total4 = n * DIM / 4;
        out_kernel<<<(total4 + 255) / 256, 256>>>(x, (float*)d_out, total4);
    }
}

// round 5
// speedup vs baseline: 1.6638x; 1.1208x over previous
#include <cuda_runtime.h>
#include <cuda_bf16.h>
#include <cstdint>

#define N_NODES_MAX 50048
#define E_MAX 1600000
#define DIM 128
#define BN_EPS 1e-5f

// ---------------- device scratch ----------------
__device__ float g_h[N_NODES_MAX * DIM];
__device__ float g_agg[N_NODES_MAX * DIM];
__device__ float g_dinv[N_NODES_MAX];
__device__ int   g_cnt[N_NODES_MAX];
__device__ int   g_row[N_NODES_MAX];
__device__ int   g_fill[N_NODES_MAX];
__device__ int   g_part[64];
__device__ int   g_esrc[E_MAX];
__device__ float g_stats[2 * DIM];

// ---------------- stream/event fork-join resources (static init) ------
struct ForkRes {
    cudaStream_t s;
    cudaEvent_t e0, e1;
    ForkRes() {
        cudaStreamCreateWithFlags(&s, cudaStreamNonBlocking);
        cudaEventCreateWithFlags(&e0, cudaEventDisableTiming);
        cudaEventCreateWithFlags(&e1, cudaEventDisableTiming);
    }
};
static ForkRes g_fork;

// ---------------- init ----------------
__global__ void init_kernel(int n) {
    int i = blockIdx.x * blockDim.x + threadIdx.x;
    if (i < n) { g_cnt[i] = 0; g_fill[i] = 0; }
    if (i < 2 * DIM) g_stats[i] = 0.0f;
}

__global__ void deg_kernel(const int* __restrict__ dst, int E) {
    int e = blockIdx.x * blockDim.x + threadIdx.x;
    if (e < E) atomicAdd(&g_cnt[dst[e]], 1);
}

// ---------------- exclusive scan (+ dinv fused) ----------------
__global__ __launch_bounds__(1024) void scan1_kernel(int n) {
    __shared__ int wsum[32];
    int i = blockIdx.x * 1024 + threadIdx.x;
    int lane = threadIdx.x & 31, wid = threadIdx.x >> 5;
    int v = (i < n) ? g_cnt[i] : 0;
    if (i < n) g_dinv[i] = rsqrtf((float)(v + 1));   // fused dinv
    int s = v;
#pragma unroll
    for (int o = 1; o < 32; o <<= 1) {
        int t = __shfl_up_sync(0xffffffffu, s, o);
        if (lane >= o) s += t;
    }
    if (lane == 31) wsum[wid] = s;
    __syncthreads();
    if (wid == 0) {
        int ws = wsum[lane];
#pragma unroll
        for (int o = 1; o < 32; o <<= 1) {
            int t = __shfl_up_sync(0xffffffffu, ws, o);
            if (lane >= o) ws += t;
        }
        wsum[lane] = ws;
    }
    __syncthreads();
    int base = (wid > 0) ? wsum[wid - 1] : 0;
    if (i < n) g_row[i] = s - v + base;
    if (threadIdx.x == 1023) g_part[blockIdx.x] = s + base;
}

// single-warp exclusive scan over <=64 block partials
__global__ void scan2_kernel(int nb) {
    int lane = threadIdx.x;
    int i0 = 2 * lane, i1 = 2 * lane + 1;
    int v0 = (i0 < nb) ? g_part[i0] : 0;
    int v1 = (i1 < nb) ? g_part[i1] : 0;
    int p = v0 + v1;
    int s = p;
#pragma unroll
    for (int o = 1; o < 32; o <<= 1) {
        int t = __shfl_up_sync(0xffffffffu, s, o);
        if (lane >= o) s += t;
    }
    int ex = s - p;
    if (i0 < nb) g_part[i0] = ex;
    if (i1 < nb) g_part[i1] = ex + v0;
}

__global__ __launch_bounds__(1024) void scan3_kernel(int n) {
    int i = blockIdx.x * 1024 + threadIdx.x;
    if (i < n) g_row[i] += g_part[blockIdx.x];
}

__global__ void fill_kernel(const int* __restrict__ src,
                            const int* __restrict__ dst, int E) {
    int e = blockIdx.x * blockDim.x + threadIdx.x;
    if (e < E) {
        int d = dst[e];
        int pos = g_row[d] + atomicAdd(&g_fill[d], 1);
        g_esrc[pos] = src[e];
    }
}

// ---------------- 3xTF32 tensor-core GEMM: h = x @ W ------------------
__device__ __forceinline__ void split_tf32(float v, uint32_t& hi, uint32_t& lo) {
    uint32_t h;
    asm("cvt.rna.tf32.f32 %0, %1;" : "=r"(h) : "f"(v));
    float lf = v - __uint_as_float(h);
    asm("cvt.rna.tf32.f32 %0, %1;" : "=r"(lo) : "f"(lf));
    hi = h;
}

__device__ __forceinline__ void mma_tf32(float* c, uint32_t a0, uint32_t a1,
                                         uint32_t a2, uint32_t a3,
                                         uint32_t b0, uint32_t b1) {
    asm volatile(
        "mma.sync.aligned.m16n8k8.row.col.f32.tf32.tf32.f32 "
        "{%0,%1,%2,%3}, {%4,%5,%6,%7}, {%8,%9}, {%0,%1,%2,%3};"
        : "+f"(c[0]), "+f"(c[1]), "+f"(c[2]), "+f"(c[3])
        : "r"(a0), "r"(a1), "r"(a2), "r"(a3), "r"(b0), "r"(b1));
}

#define KC 32
__global__ __launch_bounds__(256, 2) void gemm_tc_kernel(
    const float* __restrict__ x, const float* __restrict__ W, int n)
{
    __shared__ float xs[128][36];
    __shared__ float ws[KC][132];

    const int t = threadIdx.x;
    const int wid = t >> 5, lane = t & 31;
    const int rowg = wid & 3, colg = wid >> 2;
    const int g = lane >> 2, t4 = lane & 3;
    const int row0 = blockIdx.x * 128;

    float acc[2][8][4];
#pragma unroll
    for (int mi = 0; mi < 2; mi++)
#pragma unroll
        for (int nt = 0; nt < 8; nt++)
#pragma unroll
            for (int c = 0; c < 4; c++) acc[mi][nt][c] = 0.f;

    for (int kc = 0; kc < DIM; kc += KC) {
        for (int idx = t; idx < 1024; idx += 256) {
            int r = idx >> 3, k4 = (idx & 7) << 2;
            int row = row0 + r;
            float4 v = make_float4(0.f, 0.f, 0.f, 0.f);
            if (row < n) v = *(const float4*)(x + (size_t)row * DIM + kc + k4);
            *(float4*)&xs[r][k4] = v;
        }
        for (int idx = t; idx < 1024; idx += 256) {
            int k = idx >> 5, n4 = (idx & 31) << 2;
            *(float4*)&ws[k][n4] = *(const float4*)(W + (size_t)(kc + k) * DIM + n4);
        }
        __syncthreads();

#pragma unroll
        for (int ks = 0; ks < KC; ks += 8) {
            uint32_t ahi[2][4], alo[2][4];
#pragma unroll
            for (int mi = 0; mi < 2; mi++) {
                int rb = rowg * 32 + mi * 16;
                split_tf32(xs[rb + g][ks + t4],          ahi[mi][0], alo[mi][0]);
                split_tf32(xs[rb + g + 8][ks + t4],      ahi[mi][1], alo[mi][1]);
                split_tf32(xs[rb + g][ks + t4 + 4],      ahi[mi][2], alo[mi][2]);
                split_tf32(xs[rb + g + 8][ks + t4 + 4],  ahi[mi][3], alo[mi][3]);
            }
#pragma unroll
            for (int nt = 0; nt < 8; nt++) {
                int cb = colg * 64 + nt * 8;
                uint32_t bhi0, blo0, bhi1, blo1;
                split_tf32(ws[ks + t4][cb + g],     bhi0, blo0);
                split_tf32(ws[ks + t4 + 4][cb + g], bhi1, blo1);
#pragma unroll
                for (int mi = 0; mi < 2; mi++) {
                    mma_tf32(acc[mi][nt], ahi[mi][0], ahi[mi][1], ahi[mi][2], ahi[mi][3], bhi0, bhi1);
                    mma_tf32(acc[mi][nt], ahi[mi][0], ahi[mi][1], ahi[mi][2], ahi[mi][3], blo0, blo1);
                    mma_tf32(acc[mi][nt], alo[mi][0], alo[mi][1], alo[mi][2], alo[mi][3], bhi0, bhi1);
                }
            }
        }
        __syncthreads();
    }

#pragma unroll
    for (int mi = 0; mi < 2; mi++) {
        int rb = row0 + rowg * 32 + mi * 16;
#pragma unroll
        for (int nt = 0; nt < 8; nt++) {
            int col = colg * 64 + nt * 8 + 2 * t4;
            int r0 = rb + g, r1 = rb + g + 8;
            if (r0 < n)
                *(float2*)(g_h + (size_t)r0 * DIM + col) = make_float2(acc[mi][nt][0], acc[mi][nt][1]);
            if (r1 < n)
                *(float2*)(g_h + (size_t)r1 * DIM + col) = make_float2(acc[mi][nt][2], acc[mi][nt][3]);
        }
    }
}

// ---------------- per-node accumulate + fused BN stats ----------------
__global__ __launch_bounds__(256) void acc_kernel(const float* __restrict__ b, int n)
{
    __shared__ float ssum[8][128];
    __shared__ float ssq[8][128];
    const int w = (blockIdx.x * blockDim.x + threadIdx.x) >> 5;
    const int wid = threadIdx.x >> 5;
    const int lane = threadIdx.x & 31;

    float4 acc = make_float4(0.f, 0.f, 0.f, 0.f);
    if (w < n) {
        float di = g_dinv[w];
        float sn = di * di;
        float4 bv = __ldg((const float4*)b + lane);
        float4 hv = *((const float4*)(g_h + (size_t)w * DIM) + lane);
        acc.x = hv.x * sn + bv.x; acc.y = hv.y * sn + bv.y;
        acc.z = hv.z * sn + bv.z; acc.w = hv.w * sn + bv.w;

        const int beg = g_row[w];
        const int cnt = g_cnt[w];
        int j = 0;
        // pipelined pairs: hoist idx+norm loads ahead of row gathers
        for (; j + 2 <= cnt; j += 2) {
            int s0 = __ldg(g_esrc + beg + j);
            int s1 = __ldg(g_esrc + beg + j + 1);
            float nm0 = di * __ldg(g_dinv + s0);
            float nm1 = di * __ldg(g_dinv + s1);
            float4 v0 = __ldg((const float4*)(g_h + (size_t)s0 * DIM) + lane);
            float4 v1 = __ldg((const float4*)(g_h + (size_t)s1 * DIM) + lane);
            acc.x += v0.x * nm0; acc.y += v0.y * nm0;
            acc.z += v0.z * nm0; acc.w += v0.w * nm0;
            acc.x += v1.x * nm1; acc.y += v1.y * nm1;
            acc.z += v1.z * nm1; acc.w += v1.w * nm1;
        }
        if (j < cnt) {
            int s0 = __ldg(g_esrc + beg + j);
            float nm0 = di * __ldg(g_dinv + s0);
            float4 v0 = __ldg((const float4*)(g_h + (size_t)s0 * DIM) + lane);
            acc.x += v0.x * nm0; acc.y += v0.y * nm0;
            acc.z += v0.z * nm0; acc.w += v0.w * nm0;
        }
        *((float4*)(g_agg + (size_t)w * DIM) + lane) = acc;
    }
    *(float4*)&ssum[wid][lane * 4] = acc;
    float4 sq = make_float4(acc.x * acc.x, acc.y * acc.y, acc.z * acc.z, acc.w * acc.w);
    *(float4*)&ssq[wid][lane * 4] = sq;
    __syncthreads();

    int t = threadIdx.x;
    if (t < 128) {
        float s = 0.f;
#pragma unroll
        for (int k = 0; k < 8; k++) s += ssum[k][t];
        atomicAdd(&g_stats[t], s);
    } else {
        int d = t - 128;
        float s = 0.f;
#pragma unroll
        for (int k = 0; k < 8; k++) s += ssq[k][d];
        atomicAdd(&g_stats[DIM + d], s);
    }
}

// ---------------- epilogue: finalize fused, relu(BN(agg)) + x ---------
__global__ __launch_bounds__(256) void out_kernel(
    const float* __restrict__ x, const float* __restrict__ gamma,
    const float* __restrict__ beta, float* __restrict__ out,
    float inv_n, int total4)
{
    __shared__ float ssc[DIM];
    __shared__ float ssh[DIM];
    int t = threadIdx.x;
    if (t < DIM) {
        float mean = g_stats[t] * inv_n;
        float var  = g_stats[DIM + t] * inv_n - mean * mean;
        float sc = gamma[t] * rsqrtf(var + BN_EPS);
        ssc[t] = sc;
        ssh[t] = beta[t] - mean * sc;
    }
    __syncthreads();

    int i = blockIdx.x * blockDim.x + t;
    if (i >= total4) return;
    int d4 = i & 31;
    float4 a  = ((const float4*)g_agg)[i];
    float4 sc = *(float4*)&ssc[d4 * 4];
    float4 sh = *(float4*)&ssh[d4 * 4];
    float4 xv = ((const float4*)x)[i];
    float4 y;
    y.x = fmaxf(a.x * sc.x + sh.x, 0.f) + xv.x;
    y.y = fmaxf(a.y * sc.y + sh.y, 0.f) + xv.y;
    y.z = fmaxf(a.z * sc.z + sh.z, 0.f) + xv.z;
    y.w = fmaxf(a.w * sc.w + sh.w, 0.f) + xv.w;
    ((float4*)out)[i] = y;
}

// ---------------- launch ----------------------------------------------
extern "C" void kernel_launch(void* const* d_in, const int* in_sizes, int n_in,
                              void* d_out, int out_size)
{
    const float* x     = (const float*)d_in[0];
    const float* W     = (const float*)d_in[1];
    const float* b     = (const float*)d_in[2];
    const float* gamma = (const float*)d_in[3];
    const float* beta  = (const float*)d_in[4];
    const int*   ei    = (const int*)d_in[5];

    const int n = in_sizes[0] / DIM;
    const int E = in_sizes[5] / 2;
    const int* src = ei;
    const int* dst = ei + E;

    // fork: GEMM on side stream, overlapping the CSR build chain
    cudaEventRecord(g_fork.e0, 0);
    cudaStreamWaitEvent(g_fork.s, g_fork.e0, 0);
    gemm_tc_kernel<<<(n + 127) / 128, 256, 0, g_fork.s>>>(x, W, n);
    cudaEventRecord(g_fork.e1, g_fork.s);

    // main chain: CSR build
    init_kernel<<<(n + 255) / 256, 256>>>(n);
    deg_kernel<<<(E + 255) / 256, 256>>>(dst, E);
    int nb = (n + 1023) / 1024;
    scan1_kernel<<<nb, 1024>>>(n);          // also writes dinv
    scan2_kernel<<<1, 32>>>(nb);
    scan3_kernel<<<nb, 1024>>>(n);
    fill_kernel<<<(E + 255) / 256, 256>>>(src, dst, E);

    // join: acc needs both g_h (side) and CSR (main)
    cudaStreamWaitEvent(0, g_fork.e1, 0);
    acc_kernel<<<(n + 7) / 8, 256>>>(b, n);

    int total4 = n * DIM / 4;
    out_kernel<<<(total4 + 255) / 256, 256>>>(x, gamma, beta, (float*)d_out,
                                              1.0f / (float)n, total4);
}

// round 6
// speedup vs baseline: 1.8134x; 1.0899x over previous
#include <cuda_runtime.h>
#include <cuda_bf16.h>
#include <cuda_fp16.h>
#include <cstdint>

#define N_NODES_MAX 50048
#define E_MAX 1600000
#define DIM 128
#define BN_EPS 1e-5f

// ---------------- device scratch ----------------
__device__ __half g_h[N_NODES_MAX * DIM];     // x @ W in fp16 (gather payload)
__device__ float g_agg[N_NODES_MAX * DIM];
__device__ float g_dinv[N_NODES_MAX];
__device__ int   g_cnt[N_NODES_MAX];
__device__ int   g_row[N_NODES_MAX];          // scan -> start; after fill -> end
__device__ int   g_part[64];
__device__ int   g_esrc[E_MAX];
__device__ float g_stats[2 * DIM];

// ---------------- stream/event fork-join resources (static init) ------
struct ForkRes {
    cudaStream_t s;
    cudaEvent_t e0, e1;
    ForkRes() {
        cudaStreamCreateWithFlags(&s, cudaStreamNonBlocking);
        cudaEventCreateWithFlags(&e0, cudaEventDisableTiming);
        cudaEventCreateWithFlags(&e1, cudaEventDisableTiming);
    }
};
static ForkRes g_fork;

// ---------------- init ----------------
__global__ void init_kernel(int n) {
    int i = blockIdx.x * blockDim.x + threadIdx.x;
    if (i < n) g_cnt[i] = 0;
    if (i < 2 * DIM) g_stats[i] = 0.0f;
}

__global__ void deg_kernel(const int* __restrict__ dst, int E) {
    int e = blockIdx.x * blockDim.x + threadIdx.x;
    if (e < E) atomicAdd(&g_cnt[dst[e]], 1);
}

// ---------------- exclusive scan (+ dinv fused) ----------------
__global__ __launch_bounds__(1024) void scan1_kernel(int n) {
    __shared__ int wsum[32];
    int i = blockIdx.x * 1024 + threadIdx.x;
    int lane = threadIdx.x & 31, wid = threadIdx.x >> 5;
    int v = (i < n) ? g_cnt[i] : 0;
    if (i < n) g_dinv[i] = rsqrtf((float)(v + 1));
    int s = v;
#pragma unroll
    for (int o = 1; o < 32; o <<= 1) {
        int t = __shfl_up_sync(0xffffffffu, s, o);
        if (lane >= o) s += t;
    }
    if (lane == 31) wsum[wid] = s;
    __syncthreads();
    if (wid == 0) {
        int ws = wsum[lane];
#pragma unroll
        for (int o = 1; o < 32; o <<= 1) {
            int t = __shfl_up_sync(0xffffffffu, ws, o);
            if (lane >= o) ws += t;
        }
        wsum[lane] = ws;
    }
    __syncthreads();
    int base = (wid > 0) ? wsum[wid - 1] : 0;
    if (i < n) g_row[i] = s - v + base;
    if (threadIdx.x == 1023) g_part[blockIdx.x] = s + base;
}

__global__ void scan2_kernel(int nb) {
    int lane = threadIdx.x;
    int i0 = 2 * lane, i1 = 2 * lane + 1;
    int v0 = (i0 < nb) ? g_part[i0] : 0;
    int v1 = (i1 < nb) ? g_part[i1] : 0;
    int p = v0 + v1;
    int s = p;
#pragma unroll
    for (int o = 1; o < 32; o <<= 1) {
        int t = __shfl_up_sync(0xffffffffu, s, o);
        if (lane >= o) s += t;
    }
    int ex = s - p;
    if (i0 < nb) g_part[i0] = ex;
    if (i1 < nb) g_part[i1] = ex + v0;
}

__global__ __launch_bounds__(1024) void scan3_kernel(int n) {
    int i = blockIdx.x * 1024 + threadIdx.x;
    if (i < n) g_row[i] += g_part[blockIdx.x];
}

// fill: cursor fused into g_row (becomes end offset)
__global__ void fill_kernel(const int* __restrict__ src,
                            const int* __restrict__ dst, int E) {
    int e = blockIdx.x * blockDim.x + threadIdx.x;
    if (e < E) {
        int d = dst[e];
        int pos = atomicAdd(&g_row[d], 1);
        g_esrc[pos] = src[e];
    }
}

// ---------------- 3xTF32 tensor-core GEMM: h = x @ W (fp16 out) -------
__device__ __forceinline__ void split_tf32(float v, uint32_t& hi, uint32_t& lo) {
    uint32_t h;
    asm("cvt.rna.tf32.f32 %0, %1;" : "=r"(h) : "f"(v));
    float lf = v - __uint_as_float(h);
    asm("cvt.rna.tf32.f32 %0, %1;" : "=r"(lo) : "f"(lf));
    hi = h;
}

__device__ __forceinline__ void mma_tf32(float* c, uint32_t a0, uint32_t a1,
                                         uint32_t a2, uint32_t a3,
                                         uint32_t b0, uint32_t b1) {
    asm volatile(
        "mma.sync.aligned.m16n8k8.row.col.f32.tf32.tf32.f32 "
        "{%0,%1,%2,%3}, {%4,%5,%6,%7}, {%8,%9}, {%0,%1,%2,%3};"
        : "+f"(c[0]), "+f"(c[1]), "+f"(c[2]), "+f"(c[3])
        : "r"(a0), "r"(a1), "r"(a2), "r"(a3), "r"(b0), "r"(b1));
}

#define KC 32
__global__ __launch_bounds__(256, 2) void gemm_tc_kernel(
    const float* __restrict__ x, const float* __restrict__ W, int n)
{
    __shared__ float xs[128][36];
    __shared__ float ws[KC][132];

    const int t = threadIdx.x;
    const int wid = t >> 5, lane = t & 31;
    const int rowg = wid & 3, colg = wid >> 2;
    const int g = lane >> 2, t4 = lane & 3;
    const int row0 = blockIdx.x * 128;

    float acc[2][8][4];
#pragma unroll
    for (int mi = 0; mi < 2; mi++)
#pragma unroll
        for (int nt = 0; nt < 8; nt++)
#pragma unroll
            for (int c = 0; c < 4; c++) acc[mi][nt][c] = 0.f;

    for (int kc = 0; kc < DIM; kc += KC) {
        for (int idx = t; idx < 1024; idx += 256) {
            int r = idx >> 3, k4 = (idx & 7) << 2;
            int row = row0 + r;
            float4 v = make_float4(0.f, 0.f, 0.f, 0.f);
            if (row < n) v = *(const float4*)(x + (size_t)row * DIM + kc + k4);
            *(float4*)&xs[r][k4] = v;
        }
        for (int idx = t; idx < 1024; idx += 256) {
            int k = idx >> 5, n4 = (idx & 31) << 2;
            *(float4*)&ws[k][n4] = *(const float4*)(W + (size_t)(kc + k) * DIM + n4);
        }
        __syncthreads();

#pragma unroll
        for (int ks = 0; ks < KC; ks += 8) {
            uint32_t ahi[2][4], alo[2][4];
#pragma unroll
            for (int mi = 0; mi < 2; mi++) {
                int rb = rowg * 32 + mi * 16;
                split_tf32(xs[rb + g][ks + t4],          ahi[mi][0], alo[mi][0]);
                split_tf32(xs[rb + g + 8][ks + t4],      ahi[mi][1], alo[mi][1]);
                split_tf32(xs[rb + g][ks + t4 + 4],      ahi[mi][2], alo[mi][2]);
                split_tf32(xs[rb + g + 8][ks + t4 + 4],  ahi[mi][3], alo[mi][3]);
            }
#pragma unroll
            for (int nt = 0; nt < 8; nt++) {
                int cb = colg * 64 + nt * 8;
                uint32_t bhi0, blo0, bhi1, blo1;
                split_tf32(ws[ks + t4][cb + g],     bhi0, blo0);
                split_tf32(ws[ks + t4 + 4][cb + g], bhi1, blo1);
#pragma unroll
                for (int mi = 0; mi < 2; mi++) {
                    mma_tf32(acc[mi][nt], ahi[mi][0], ahi[mi][1], ahi[mi][2], ahi[mi][3], bhi0, bhi1);
                    mma_tf32(acc[mi][nt], ahi[mi][0], ahi[mi][1], ahi[mi][2], ahi[mi][3], blo0, blo1);
                    mma_tf32(acc[mi][nt], alo[mi][0], alo[mi][1], alo[mi][2], alo[mi][3], bhi0, bhi1);
                }
            }
        }
        __syncthreads();
    }

#pragma unroll
    for (int mi = 0; mi < 2; mi++) {
        int rb = row0 + rowg * 32 + mi * 16;
#pragma unroll
        for (int nt = 0; nt < 8; nt++) {
            int col = colg * 64 + nt * 8 + 2 * t4;
            int r0 = rb + g, r1 = rb + g + 8;
            if (r0 < n)
                *(__half2*)(g_h + (size_t)r0 * DIM + col) =
                    __floats2half2_rn(acc[mi][nt][0], acc[mi][nt][1]);
            if (r1 < n)
                *(__half2*)(g_h + (size_t)r1 * DIM + col) =
                    __floats2half2_rn(acc[mi][nt][2], acc[mi][nt][3]);
        }
    }
}

// ---------------- per-node accumulate + fused BN stats ----------------
__device__ __forceinline__ void fma_row(float4& acc, uint2 raw, float nm) {
    __half2 p0 = *(__half2*)&raw.x, p1 = *(__half2*)&raw.y;
    float2 f0 = __half22float2(p0), f1 = __half22float2(p1);
    acc.x += f0.x * nm; acc.y += f0.y * nm;
    acc.z += f1.x * nm; acc.w += f1.y * nm;
}

__global__ __launch_bounds__(256) void acc_kernel(const float* __restrict__ b, int n)
{
    __shared__ float ssum[8][128];
    __shared__ float ssq[8][128];
    const int w = (blockIdx.x * blockDim.x + threadIdx.x) >> 5;
    const int wid = threadIdx.x >> 5;
    const int lane = threadIdx.x & 31;

    float4 acc = make_float4(0.f, 0.f, 0.f, 0.f);
    if (w < n) {
        float di = g_dinv[w];
        float4 bv = __ldg((const float4*)b + lane);
        acc = bv;
        // self loop (norm = dinv^2)
        {
            uint2 raw = __ldg((const uint2*)(g_h + (size_t)w * DIM) + lane);
            fma_row(acc, raw, di * di);
        }
        const int end = g_row[w];       // post-fill end offset
        const int cnt = g_cnt[w];
        const int beg = end - cnt;
        int j = 0;
        for (; j + 4 <= cnt; j += 4) {
            int s0 = __ldg(g_esrc + beg + j);
            int s1 = __ldg(g_esrc + beg + j + 1);
            int s2 = __ldg(g_esrc + beg + j + 2);
            int s3 = __ldg(g_esrc + beg + j + 3);
            float nm0 = di * __ldg(g_dinv + s0);
            float nm1 = di * __ldg(g_dinv + s1);
            float nm2 = di * __ldg(g_dinv + s2);
            float nm3 = di * __ldg(g_dinv + s3);
            uint2 r0 = __ldg((const uint2*)(g_h + (size_t)s0 * DIM) + lane);
            uint2 r1 = __ldg((const uint2*)(g_h + (size_t)s1 * DIM) + lane);
            uint2 r2 = __ldg((const uint2*)(g_h + (size_t)s2 * DIM) + lane);
            uint2 r3 = __ldg((const uint2*)(g_h + (size_t)s3 * DIM) + lane);
            fma_row(acc, r0, nm0);
            fma_row(acc, r1, nm1);
            fma_row(acc, r2, nm2);
            fma_row(acc, r3, nm3);
        }
        for (; j < cnt; j++) {
            int s0 = __ldg(g_esrc + beg + j);
            float nm0 = di * __ldg(g_dinv + s0);
            uint2 r0 = __ldg((const uint2*)(g_h + (size_t)s0 * DIM) + lane);
            fma_row(acc, r0, nm0);
        }
        *((float4*)(g_agg + (size_t)w * DIM) + lane) = acc;
    }
    *(float4*)&ssum[wid][lane * 4] = acc;
    float4 sq = make_float4(acc.x * acc.x, acc.y * acc.y, acc.z * acc.z, acc.w * acc.w);
    *(float4*)&ssq[wid][lane * 4] = sq;
    __syncthreads();

    int t = threadIdx.x;
    if (t < 128) {
        float s = 0.f;
#pragma unroll
        for (int k = 0; k < 8; k++) s += ssum[k][t];
        atomicAdd(&g_stats[t], s);
    } else {
        int d = t - 128;
        float s = 0.f;
#pragma unroll
        for (int k = 0; k < 8; k++) s += ssq[k][d];
        atomicAdd(&g_stats[DIM + d], s);
    }
}

// ---------------- epilogue: finalize fused, relu(BN(agg)) + x ---------
__global__ __launch_bounds__(256) void out_kernel(
    const float* __restrict__ x, const float* __restrict__ gamma,
    const float* __restrict__ beta, float* __restrict__ out,
    float inv_n, int total4)
{
    __shared__ float ssc[DIM];
    __shared__ float ssh[DIM];
    int t = threadIdx.x;
    if (t < DIM) {
        float mean = g_stats[t] * inv_n;
        float var  = g_stats[DIM + t] * inv_n - mean * mean;
        float sc = gamma[t] * rsqrtf(var + BN_EPS);
        ssc[t] = sc;
        ssh[t] = beta[t] - mean * sc;
    }
    __syncthreads();

    int i = blockIdx.x * blockDim.x + t;
    if (i >= total4) return;
    int d4 = i & 31;
    float4 a  = ((const float4*)g_agg)[i];
    float4 sc = *(float4*)&ssc[d4 * 4];
    float4 sh = *(float4*)&ssh[d4 * 4];
    float4 xv = ((const float4*)x)[i];
    float4 y;
    y.x = fmaxf(a.x * sc.x + sh.x, 0.f) + xv.x;
    y.y = fmaxf(a.y * sc.y + sh.y, 0.f) + xv.y;
    y.z = fmaxf(a.z * sc.z + sh.z, 0.f) + xv.z;
    y.w = fmaxf(a.w * sc.w + sh.w, 0.f) + xv.w;
    ((float4*)out)[i] = y;
}

// ---------------- launch ----------------------------------------------
extern "C" void kernel_launch(void* const* d_in, const int* in_sizes, int n_in,
                              void* d_out, int out_size)
{
    const float* x     = (const float*)d_in[0];
    const float* W     = (const float*)d_in[1];
    const float* b     = (const float*)d_in[2];
    const float* gamma = (const float*)d_in[3];
    const float* beta  = (const float*)d_in[4];
    const int*   ei    = (const int*)d_in[5];

    const int n = in_sizes[0] / DIM;
    const int E = in_sizes[5] / 2;
    const int* src = ei;
    const int* dst = ei + E;

    // fork: GEMM on side stream, overlapping the CSR build chain
    cudaEventRecord(g_fork.e0, 0);
    cudaStreamWaitEvent(g_fork.s, g_fork.e0, 0);
    gemm_tc_kernel<<<(n + 127) / 128, 256, 0, g_fork.s>>>(x, W, n);
    cudaEventRecord(g_fork.e1, g_fork.s);

    // main chain: CSR build
    init_kernel<<<(n + 255) / 256, 256>>>(n);
    deg_kernel<<<(E + 255) / 256, 256>>>(dst, E);
    int nb = (n + 1023) / 1024;
    scan1_kernel<<<nb, 1024>>>(n);          // also writes dinv
    scan2_kernel<<<1, 32>>>(nb);
    scan3_kernel<<<nb, 1024>>>(n);
    fill_kernel<<<(E + 255) / 256, 256>>>(src, dst, E);

    // join: acc needs both g_h (side) and CSR (main)
    cudaStreamWaitEvent(0, g_fork.e1, 0);
    acc_kernel<<<(n + 7) / 8, 256>>>(b, n);

    int total4 = n * DIM / 4;
    out_kernel<<<(total4 + 255) / 256, 256>>>(x, gamma, beta, (float*)d_out,
                                              1.0f / (float)n, total4);
}